// round 16
// baseline (speedup 1.0000x reference)
#include <cuda_runtime.h>
#include <math.h>

#define H 8192
#define NSPLIT 64
#define COLBLKS 8
#define NBLK (NSPLIT * COLBLKS)       // 512 blocks
#define RPH (H / NBLK)                // 16 h1 rows per block (phase 1)
#define MAX_RPS 128
#define UNROLL 8
#define CACHE_LIM 64                  // (row & 127) < 64 -> L2-cached resident set
#define K3_BLOCKS 128
#define K3_COLS 64
#define K3_GRPS 4
#define K3_PER_GRP (NSPLIT / K3_GRPS) // 16

// Scratch (no cudaMalloc allowed)
__device__ float g_tmpx[H];                 // per-block local compactions
__device__ int   g_tmpi[H];
__device__ int   g_cnt[NBLK];               // per-block nonzero counts
__device__ float g_xc[H];                   // globally compacted values
__device__ int   g_ic[H];                   // globally compacted row indices
__device__ int   g_nnz;
__device__ int   g_ph1;                     // phase-1 arrival counter (self-resets)
__device__ volatile int g_flag;             // compaction-done flag (k3 resets)
__device__ float g_part[NSPLIT * H];        // layer-2 partials (2 MB, L2)
__device__ float g_pen_part[K3_BLOCKS * 8]; // head partials
__device__ int   g_done_cnt;                // k3 completion counter

// ---- k2: in-kernel global compaction (1 sync) + balanced sparse GEMV ----
__global__ void __launch_bounds__(256, 4) k2_fused(const float* __restrict__ state,
                                                   const float* __restrict__ W1,
                                                   const float* __restrict__ b1,
                                                   const float* __restrict__ W2) {
    __shared__ float s[42];
    __shared__ float xs[MAX_RPS];
    __shared__ int   ridx[MAX_RPS];
    __shared__ int   c1[4], c2[4];
    __shared__ int   sh_last;
    int t = threadIdx.x;
    int lane = t & 31, wid = t >> 5;
    if (t < 42) s[t] = state[t];
    __syncthreads();

    int fb = blockIdx.y * COLBLKS + blockIdx.x;   // 0..511

    // ---- Phase 1: 16 h1 rows per block, local order-preserving compaction ----
    if (wid == 0) {
        float v = 0.0f; bool nz = false;
        int row = fb * RPH + lane;
        if (lane < RPH) {
            float acc = b1[row];
            #pragma unroll
            for (int k = 0; k < 42; k++)
                acc = fmaf(s[k], __ldg(W1 + (size_t)k * H + row), acc);
            v = fmaxf(acc, 0.0f);
            nz = (v > 0.0f);
        }
        unsigned m = __ballot_sync(0xFFFFFFFF, nz);
        if (nz) {
            int off = __popc(m & ((1u << lane) - 1));
            g_tmpx[fb * RPH + off] = v;
            g_tmpi[fb * RPH + off] = row;
        }
        if (lane == 0) g_cnt[fb] = __popc(m);
    }
    __threadfence();
    __syncthreads();
    if (t == 0) {
        int old = atomicAdd(&g_ph1, 1);
        sh_last = (old == NBLK - 1);
        if (sh_last) g_ph1 = 0;                    // self-reset for next replay
    }
    __syncthreads();

    if (sh_last) {
        // ---- last arriver: 512-entry prefix scan + gather + flag ----
        __shared__ int spref[NBLK];
        __shared__ int scnt[NBLK];
        __shared__ int wtot[8];
        int cA = g_cnt[2 * t], cB = g_cnt[2 * t + 1];
        scnt[2 * t] = cA;  scnt[2 * t + 1] = cB;
        int pairsum = cA + cB;
        int x = pairsum;
        #pragma unroll
        for (int d = 1; d < 32; d <<= 1) {
            int y = __shfl_up_sync(0xFFFFFFFF, x, d);
            if (lane >= d) x += y;
        }
        if (lane == 31) wtot[wid] = x;
        __syncthreads();
        if (wid == 0) {
            int w = (lane < 8) ? wtot[lane] : 0;
            #pragma unroll
            for (int d = 1; d < 8; d <<= 1) {
                int y = __shfl_up_sync(0xFFFFFFFF, w, d);
                if (lane >= d) w += y;
            }
            if (lane < 8) wtot[lane] = w;
        }
        __syncthreads();
        int excl = (x - pairsum) + (wid > 0 ? wtot[wid - 1] : 0);
        spref[2 * t] = excl;
        spref[2 * t + 1] = excl + cA;
        if (t == 255) g_nnz = excl + pairsum;      // grand total
        __syncthreads();
        for (int idx = t; idx < H; idx += 256) {
            int b = idx >> 4, i = idx & 15;
            if (i < scnt[b]) {
                g_xc[spref[b] + i] = g_tmpx[idx];
                g_ic[spref[b] + i] = g_tmpi[idx];
            }
        }
        __threadfence();
        __syncthreads();
        if (t == 0) g_flag = 1;                    // release
    } else {
        if (t == 0) { while (g_flag == 0) __nanosleep(64); }
        __syncthreads();
        __threadfence();                           // acquire
    }

    // ---- Phase 2: perfectly balanced sparse split-K GEMV ----
    int nnz = g_nnz;
    int rps = (nnz + NSPLIT - 1) / NSPLIT;         // <= 128
    int rbeg = blockIdx.y * rps;
    int rend = min(rbeg + rps, nnz);
    int nr = rend - rbeg; if (nr < 0) nr = 0;

    float vv = 0.0f; int row = 0;
    if (t < nr) { vv = g_xc[rbeg + t]; row = g_ic[rbeg + t]; }
    bool cach = (t < nr) && ((row & 127) < CACHE_LIM);
    bool strm = (t < nr) && ((row & 127) >= CACHE_LIM);
    unsigned m1 = __ballot_sync(0xFFFFFFFF, cach);
    unsigned m2 = __ballot_sync(0xFFFFFFFF, strm);
    if (lane == 0 && wid < 4) { c1[wid] = __popc(m1); c2[wid] = __popc(m2); }
    __syncthreads();
    int nc = c1[0] + c1[1] + c1[2] + c1[3];
    int ns = c2[0] + c2[1] + c2[2] + c2[3];
    unsigned lt = (1u << lane) - 1;
    if (cach) {
        int off = __popc(m1 & lt);
        for (int w = 0; w < 4; w++) if (w < wid) off += c1[w];
        xs[off] = vv;  ridx[off] = row;
    }
    if (strm) {
        int off = nc + __popc(m2 & lt);
        for (int w = 0; w < 4; w++) if (w < wid) off += c2[w];
        xs[off] = vv;  ridx[off] = row;
    }
    __syncthreads();

    int c = (blockIdx.x * 256 + t) * 4;
    float4 acc = make_float4(0.f, 0.f, 0.f, 0.f);

    // cached list: default caching -> L2-resident across graph replays
    int nc8 = nc & ~(UNROLL - 1);
    for (int rb = 0; rb < nc8; rb += UNROLL) {
        float4 w[UNROLL];
        #pragma unroll
        for (int u = 0; u < UNROLL; u++)
            w[u] = __ldg(reinterpret_cast<const float4*>(
                       W2 + (size_t)ridx[rb + u] * H + c));
        #pragma unroll
        for (int u = 0; u < UNROLL; u++) {
            float xv = xs[rb + u];
            acc.x = fmaf(xv, w[u].x, acc.x);
            acc.y = fmaf(xv, w[u].y, acc.y);
            acc.z = fmaf(xv, w[u].z, acc.z);
            acc.w = fmaf(xv, w[u].w, acc.w);
        }
    }
    for (int r = nc8; r < nc; r++) {
        float4 w = __ldg(reinterpret_cast<const float4*>(
                       W2 + (size_t)ridx[r] * H + c));
        float xv = xs[r];
        acc.x = fmaf(xv, w.x, acc.x);  acc.y = fmaf(xv, w.y, acc.y);
        acc.z = fmaf(xv, w.z, acc.z);  acc.w = fmaf(xv, w.w, acc.w);
    }

    // streamed list: evict-first
    int ne = nc + ns;
    int ns8 = nc + ((ne - nc) & ~(UNROLL - 1));
    for (int rb = nc; rb < ns8; rb += UNROLL) {
        float4 w[UNROLL];
        #pragma unroll
        for (int u = 0; u < UNROLL; u++)
            w[u] = __ldcs(reinterpret_cast<const float4*>(
                       W2 + (size_t)ridx[rb + u] * H + c));
        #pragma unroll
        for (int u = 0; u < UNROLL; u++) {
            float xv = xs[rb + u];
            acc.x = fmaf(xv, w[u].x, acc.x);
            acc.y = fmaf(xv, w[u].y, acc.y);
            acc.z = fmaf(xv, w[u].z, acc.z);
            acc.w = fmaf(xv, w[u].w, acc.w);
        }
    }
    for (int r = ns8; r < ne; r++) {
        float4 w = __ldcs(reinterpret_cast<const float4*>(
                       W2 + (size_t)ridx[r] * H + c));
        float xv = xs[r];
        acc.x = fmaf(xv, w.x, acc.x);  acc.y = fmaf(xv, w.y, acc.y);
        acc.z = fmaf(xv, w.z, acc.z);  acc.w = fmaf(xv, w.w, acc.w);
    }

    *reinterpret_cast<float4*>(g_part + (size_t)blockIdx.y * H + c) = acc;
}

// ---- k3: 128-block parallel reduce + W3 head + last-arriver softmax ----
__global__ void __launch_bounds__(256) k3(const float* __restrict__ state,
                                          const float* __restrict__ b2,
                                          const float* __restrict__ W3,
                                          const float* __restrict__ b3,
                                          float* __restrict__ out) {
    __shared__ float gsum[K3_GRPS][K3_COLS];
    __shared__ float red[K3_COLS][8];
    __shared__ int   flag;
    int t = threadIdx.x;
    int cl = t & (K3_COLS - 1);
    int gp = t >> 6;
    int j = blockIdx.x * K3_COLS + cl;

    if (blockIdx.x == 0 && t == 0) g_flag = 0;   // reset k2 handshake for next replay

    float p[K3_PER_GRP];
    #pragma unroll
    for (int u = 0; u < K3_PER_GRP; u++)
        p[u] = g_part[(size_t)(gp * K3_PER_GRP + u) * H + j];
    float a0 = 0.f, a1 = 0.f, a2 = 0.f, a3 = 0.f;
    #pragma unroll
    for (int u = 0; u < K3_PER_GRP; u += 4) {
        a0 += p[u]; a1 += p[u + 1]; a2 += p[u + 2]; a3 += p[u + 3];
    }
    gsum[gp][cl] = (a0 + a1) + (a2 + a3);
    __syncthreads();

    if (t < K3_COLS) {
        float h2 = fmaxf(b2[j] + ((gsum[0][cl] + gsum[1][cl]) +
                                  (gsum[2][cl] + gsum[3][cl])), 0.0f);
        float4 w0 = *reinterpret_cast<const float4*>(W3 + (size_t)j * 8);
        float4 w1 = *reinterpret_cast<const float4*>(W3 + (size_t)j * 8 + 4);
        red[cl][0] = h2 * w0.x;  red[cl][1] = h2 * w0.y;
        red[cl][2] = h2 * w0.z;  red[cl][3] = h2 * w0.w;
        red[cl][4] = h2 * w1.x;  red[cl][5] = h2 * w1.y;
        red[cl][6] = h2 * w1.z;  red[cl][7] = h2 * w1.w;
    }
    __syncthreads();

    for (int stride = K3_COLS / 2; stride > 0; stride >>= 1) {
        if (t < stride) {
            #pragma unroll
            for (int n = 0; n < 8; n++) red[t][n] += red[t + stride][n];
        }
        __syncthreads();
    }
    if (t < 8) g_pen_part[blockIdx.x * 8 + t] = red[0][t];

    __syncthreads();
    __threadfence();
    if (t == 0) {
        int old = atomicAdd(&g_done_cnt, 1);
        flag = (old == K3_BLOCKS - 1);
        if (flag) g_done_cnt = 0;
    }
    __syncthreads();
    if (!flag) return;
    __threadfence();

    __shared__ float psum[8][8];
    if (t < 64) {
        int n = t & 7, ch = t >> 3;
        float a = 0.0f;
        #pragma unroll
        for (int b = 0; b < K3_BLOCKS / 8; b++)
            a += g_pen_part[(ch * (K3_BLOCKS / 8) + b) * 8 + n];
        psum[ch][n] = a;
    }
    __syncthreads();

    if (t == 0) {
        float pens[8];
        #pragma unroll
        for (int n = 0; n < 8; n++) {
            float a = b3[n];
            #pragma unroll
            for (int ch = 0; ch < 8; ch++) a += psum[ch][n];
            pens[n] = a;
        }
        float value = pens[7];
        bool legal[7];
        float mx = -INFINITY;
        #pragma unroll
        for (int n = 0; n < 7; n++) {
            legal[n] = (state[n] == 0.0f);
            if (legal[n] && pens[n] > mx) mx = pens[n];
        }
        float e[7];
        float sum = 0.0f;
        #pragma unroll
        for (int n = 0; n < 7; n++) {
            e[n] = legal[n] ? expf(pens[n] - mx) : 0.0f;
            sum += e[n];
        }
        float inv = 1.0f / sum;
        out[0] = value;
        #pragma unroll
        for (int n = 0; n < 7; n++) out[1 + n] = e[n] * inv;
    }
}

extern "C" void kernel_launch(void* const* d_in, const int* in_sizes, int n_in,
                              void* d_out, int out_size) {
    const float* state = (const float*)d_in[0];
    const float* W1    = (const float*)d_in[1];
    const float* b1    = (const float*)d_in[2];
    const float* W2    = (const float*)d_in[3];
    const float* b2    = (const float*)d_in[4];
    const float* W3    = (const float*)d_in[5];
    const float* b3    = (const float*)d_in[6];
    float* out = (float*)d_out;

    dim3 g2(COLBLKS, NSPLIT);             // (8, 64) = 512 blocks, all resident
    k2_fused<<<g2, 256>>>(state, W1, b1, W2);

    k3<<<K3_BLOCKS, 256>>>(state, b2, W3, b3, out);
}